// round 1
// baseline (speedup 1.0000x reference)
#include <cuda_runtime.h>
#include <math_constants.h>

// ---------------------------------------------------------------------------
// Dynamic multi-teacher KD loss, fused.
//   Inputs (metadata order): outputs1..4, out_s  [8192,1000] f32 ; targets [8192] i32
//   Output: scalar f32 mean loss.
//
// Kernel 1 (one block / row): computes per-row {CE, thr[5], g[5], KD[5]} and
//   atomically accumulates global min(gathered of 4 teachers) and
//   global max(all logits of 4 teachers) using order-monotone uint encoding
//   (min/max atomics are order-independent -> deterministic).
// Kernel 2: applies shift/max_preds weights, reduces sum.
// Kernel 3: writes mean.
// ---------------------------------------------------------------------------

namespace {
constexpr int NB   = 8192;   // batch
constexpr int NC   = 1000;   // classes
constexpr int NV4  = 250;    // float4s per row
constexpr float INV_TKD = 1.0f / 20.0f;
constexpr float TKD2    = 400.0f;      // T_KD^2
constexpr float INV_TTHR = 1.0f / 6.0f;
}

__device__ float    g_rowbuf[NB * 16];
__device__ unsigned g_minEnc;
__device__ unsigned g_maxEnc;
__device__ float    g_sum;

__device__ __forceinline__ unsigned encF(float f) {
    unsigned u = __float_as_uint(f);
    return (u & 0x80000000u) ? ~u : (u | 0x80000000u);
}
__device__ __forceinline__ float decF(unsigned e) {
    return __uint_as_float((e & 0x80000000u) ? (e ^ 0x80000000u) : ~e);
}

__global__ void init_k() {
    g_minEnc = encF(CUDART_INF_F);    // identity for min
    g_maxEnc = encF(-CUDART_INF_F);   // identity for max
    g_sum    = 0.0f;
}

// top-2 merge: (m1,m2) <- top2 of {m1,m2,b1,b2}; duplicates allowed (matches top_k)
__device__ __forceinline__ void merge2(float& m1, float& m2, float b1, float b2) {
    if (b1 > m1) { m2 = fmaxf(m1, b2); m1 = b1; }
    else         { m2 = fmaxf(m2, b1); }
}

__global__ __launch_bounds__(256) void row_kernel(
    const float* __restrict__ o1, const float* __restrict__ o2,
    const float* __restrict__ o3, const float* __restrict__ o4,
    const float* __restrict__ os, const int* __restrict__ tgts)
{
    __shared__ float4 sm[6][NV4];            // t1..t4, mimic, student
    __shared__ float  s_m1[5][8], s_m2[5][8], s_ms[8];
    __shared__ float  s_sum[17][8];
    __shared__ float  b_m1[5];
    __shared__ float  b_ms;

    const int row  = blockIdx.x;
    const int t    = threadIdx.x;
    const int lane = t & 31;
    const int wid  = t >> 5;
    const size_t base = (size_t)row * NC;

    // ---- load 5 rows, build mimic, stage in smem ----
    if (t < NV4) {
        float4 a = reinterpret_cast<const float4*>(o1 + base)[t];
        float4 b = reinterpret_cast<const float4*>(o2 + base)[t];
        float4 c = reinterpret_cast<const float4*>(o3 + base)[t];
        float4 d = reinterpret_cast<const float4*>(o4 + base)[t];
        float4 s = reinterpret_cast<const float4*>(os + base)[t];
        float4 m;
        m.x = (((a.x + b.x) + c.x) + d.x) * 0.25f;
        m.y = (((a.y + b.y) + c.y) + d.y) * 0.25f;
        m.z = (((a.z + b.z) + c.z) + d.z) * 0.25f;
        m.w = (((a.w + b.w) + c.w) + d.w) * 0.25f;
        sm[0][t] = a; sm[1][t] = b; sm[2][t] = c; sm[3][t] = d;
        sm[4][t] = m; sm[5][t] = s;
    }
    __syncthreads();

    // ---- phase A: per-branch top-2, student max ----
    float m1[5], m2[5], ms = -CUDART_INF_F;
#pragma unroll
    for (int b = 0; b < 5; b++) { m1[b] = -CUDART_INF_F; m2[b] = -CUDART_INF_F; }
    if (t < NV4) {
#pragma unroll
        for (int b = 0; b < 5; b++) {
            float4 v = sm[b][t];
            merge2(m1[b], m2[b], v.x, -CUDART_INF_F);
            merge2(m1[b], m2[b], v.y, -CUDART_INF_F);
            merge2(m1[b], m2[b], v.z, -CUDART_INF_F);
            merge2(m1[b], m2[b], v.w, -CUDART_INF_F);
        }
        float4 v = sm[5][t];
        ms = fmaxf(fmaxf(v.x, v.y), fmaxf(v.z, v.w));
    }
#pragma unroll
    for (int off = 16; off; off >>= 1) {
#pragma unroll
        for (int b = 0; b < 5; b++) {
            float a1 = __shfl_xor_sync(0xffffffffu, m1[b], off);
            float a2 = __shfl_xor_sync(0xffffffffu, m2[b], off);
            merge2(m1[b], m2[b], a1, a2);
        }
        ms = fmaxf(ms, __shfl_xor_sync(0xffffffffu, ms, off));
    }
    if (lane == 0) {
#pragma unroll
        for (int b = 0; b < 5; b++) { s_m1[b][wid] = m1[b]; s_m2[b][wid] = m2[b]; }
        s_ms[wid] = ms;
    }
    __syncthreads();

    float fm1[5], fm2[5], fms = -CUDART_INF_F;   // only valid on thread 0
    if (t == 0) {
#pragma unroll
        for (int b = 0; b < 5; b++) {
            fm1[b] = s_m1[b][0]; fm2[b] = s_m2[b][0];
            for (int w = 1; w < 8; w++) merge2(fm1[b], fm2[b], s_m1[b][w], s_m2[b][w]);
            b_m1[b] = fm1[b];
        }
        fms = s_ms[0];
        for (int w = 1; w < 8; w++) fms = fmaxf(fms, s_ms[w]);
        b_ms = fms;
    }
    __syncthreads();

    float lm1[5];
#pragma unroll
    for (int b = 0; b < 5; b++) lm1[b] = b_m1[b];
    const float lms = b_ms;

    // ---- phase B: exp-sums ----
    float acc[17];
#pragma unroll
    for (int q = 0; q < 17; q++) acc[q] = 0.0f;
    // acc: [0..4]=E, [5..9]=S1, [10..14]=S2, [15]=Es1, [16]=EsT
    if (t < NV4) {
        float4 sv = sm[5][t];
        float sarr[4] = { sv.x, sv.y, sv.z, sv.w };
#pragma unroll
        for (int b = 0; b < 5; b++) {
            float4 v = sm[b][t];
            float varr[4] = { v.x, v.y, v.z, v.w };
            float mb = lm1[b];
#pragma unroll
            for (int j = 0; j < 4; j++) {
                float e = __expf((varr[j] - mb) * INV_TKD);
                acc[b]      += e;
                acc[5 + b]  += e * varr[j] * INV_TKD;
                acc[10 + b] += e * sarr[j] * INV_TKD;
            }
        }
#pragma unroll
        for (int j = 0; j < 4; j++) {
            acc[15] += __expf(sarr[j] - lms);
            acc[16] += __expf((sarr[j] - lms) * INV_TKD);
        }
    }
#pragma unroll
    for (int off = 16; off; off >>= 1) {
#pragma unroll
        for (int q = 0; q < 17; q++)
            acc[q] += __shfl_xor_sync(0xffffffffu, acc[q], off);
    }
    if (lane == 0) {
#pragma unroll
        for (int q = 0; q < 17; q++) s_sum[q][wid] = acc[q];
    }
    __syncthreads();

    // ---- thread 0: finalize row ----
    if (t == 0) {
        float tot[17];
#pragma unroll
        for (int q = 0; q < 17; q++) {
            float v = s_sum[q][0];
            for (int w = 1; w < 8; w++) v += s_sum[q][w];
            tot[q] = v;
        }

        const int tg = tgts[row];
        const float* smf = reinterpret_cast<const float*>(sm);
        float g[5];
#pragma unroll
        for (int b = 0; b < 5; b++) g[b] = smf[b * NC + tg];
        float zst = smf[5 * NC + tg];

        // margins (shift-invariant) + threshold softmax (T=6)
        float mg[5], mx = -CUDART_INF_F;
#pragma unroll
        for (int b = 0; b < 5; b++) {
            mg[b] = (fm1[b] == g[b]) ? (fm1[b] - fm2[b]) : 0.0f;
            mx = fmaxf(mx, mg[b]);
        }
        float te[5], ts = 0.0f;
#pragma unroll
        for (int b = 0; b < 5; b++) { te[b] = __expf((mg[b] - mx) * INV_TTHR); ts += te[b]; }
        float invts = 1.0f / ts;

        // student: CE (T=1) and lse at T=20
        float CE    = fms + __logf(tot[15]) - zst;
        float lseT  = fms * INV_TKD + __logf(tot[16]);

        float* rb = g_rowbuf + (size_t)row * 16;
        rb[0] = CE;
#pragma unroll
        for (int b = 0; b < 5; b++) {
            float E  = tot[b];
            float iE = 1.0f / E;
            float KD = TKD2 * (tot[5 + b] * iE - fm1[b] * INV_TKD - __logf(E)
                               - tot[10 + b] * iE + lseT);
            rb[1 + b]  = te[b] * invts;   // threshold weight
            rb[6 + b]  = g[b];            // gathered (unshifted)
            rb[11 + b] = KD;
        }

        // global reductions over the 4 REAL teachers only
        float gmin4 = fminf(fminf(g[0], g[1]), fminf(g[2], g[3]));
        float mmax4 = fmaxf(fmaxf(fm1[0], fm1[1]), fmaxf(fm1[2], fm1[3]));
        atomicMin(&g_minEnc, encF(gmin4));
        atomicMax(&g_maxEnc, encF(mmax4));
    }
}

__global__ __launch_bounds__(256) void reduce_kernel() {
    __shared__ float rs[8];
    const float Cv = decF(g_minEnc);
    const float Mv = decF(g_maxEnc);
    const float shift = (Cv < 0.0f) ? (-Cv + 1e-5f) : 0.0f;
    const float inv   = 1.0f / (Mv + shift);

    int row = blockIdx.x * 256 + threadIdx.x;
    float loss = 0.0f;
    if (row < NB) {
        const float* r = g_rowbuf + (size_t)row * 16;
        float4 q0 = *reinterpret_cast<const float4*>(r);
        float4 q1 = *reinterpret_cast<const float4*>(r + 4);
        float4 q2 = *reinterpret_cast<const float4*>(r + 8);
        float4 q3 = *reinterpret_cast<const float4*>(r + 12);
        float a[16] = { q0.x,q0.y,q0.z,q0.w, q1.x,q1.y,q1.z,q1.w,
                        q2.x,q2.y,q2.z,q2.w, q3.x,q3.y,q3.z,q3.w };
        float CE = a[0];
#pragma unroll
        for (int b = 0; b < 5; b++) {
            float w2 = (a[6 + b] + shift) * inv;
            loss += a[1 + b] * ((1.0f - w2) * CE + w2 * a[11 + b]);
        }
    }
#pragma unroll
    for (int off = 16; off; off >>= 1)
        loss += __shfl_xor_sync(0xffffffffu, loss, off);
    if ((threadIdx.x & 31) == 0) rs[threadIdx.x >> 5] = loss;
    __syncthreads();
    if (threadIdx.x == 0) {
        float s = rs[0];
        for (int w = 1; w < 8; w++) s += rs[w];
        atomicAdd(&g_sum, s);
    }
}

__global__ void final_k(float* __restrict__ out) {
    out[0] = g_sum * (1.0f / (float)NB);
}

extern "C" void kernel_launch(void* const* d_in, const int* in_sizes, int n_in,
                              void* d_out, int out_size) {
    const float* o1 = (const float*)d_in[0];
    const float* o2 = (const float*)d_in[1];
    const float* o3 = (const float*)d_in[2];
    const float* o4 = (const float*)d_in[3];
    const float* os = (const float*)d_in[4];
    const int*   tg = (const int*)d_in[5];
    (void)in_sizes; (void)n_in; (void)out_size;

    init_k<<<1, 1>>>();
    row_kernel<<<NB, 256>>>(o1, o2, o3, o4, os, tg);
    reduce_kernel<<<(NB + 255) / 256, 256>>>();
    final_k<<<1, 1>>>((float*)d_out);
}

// round 2
// speedup vs baseline: 1.7690x; 1.7690x over previous
#include <cuda_runtime.h>
#include <math_constants.h>

// Warp-per-row fused multi-teacher KD loss.
// Single pass: each warp streams its row of all 5 tensors once from HBM,
// accumulating (without max-subtraction -- safe for |z|<~80 at T=20, |z|<~80 at T=1):
//   per branch b in {t1..t4, mimic}: E=sum e^(z/20), S1=sum e*z/20, S2=sum e*zs/20,
//   top-2 logits (for margins), plus student sum e^zs, sum e^(zs/20).
// Target logits captured in-loop and broadcast by shuffle (no second gather read).
// Global min(gathered)/max(logits) of the 4 real teachers via block-prereduced
// encoded-uint RED min/max (order-independent -> deterministic).

namespace {
constexpr int NB = 8192;
constexpr int NC = 1000;
constexpr int NV4 = 250;                 // float4 per row
constexpr float ITKD  = 1.0f / 20.0f;
constexpr float TKD2  = 400.0f;
constexpr float ITTHR = 1.0f / 6.0f;
}

__device__ float    g_rowbuf[NB * 16];
__device__ unsigned g_minEnc;
__device__ unsigned g_maxEnc;
__device__ float    g_sum;

__device__ __forceinline__ unsigned encF(float f) {
    unsigned u = __float_as_uint(f);
    return (u & 0x80000000u) ? ~u : (u | 0x80000000u);
}
__device__ __forceinline__ float decF(unsigned e) {
    return __uint_as_float((e & 0x80000000u) ? (e ^ 0x80000000u) : ~e);
}

__global__ void init_k() {
    g_minEnc = encF(CUDART_INF_F);
    g_maxEnc = encF(-CUDART_INF_F);
    g_sum    = 0.0f;
}

// streaming/cross-lane top-2 merge
__device__ __forceinline__ void merge2(float& m1, float& m2, float b1, float b2) {
    if (b1 > m1) { m2 = fmaxf(m1, b2); m1 = b1; }
    else         { m2 = fmaxf(m2, b1); }
}

__global__ __launch_bounds__(256) void row_kernel(
    const float* __restrict__ o1, const float* __restrict__ o2,
    const float* __restrict__ o3, const float* __restrict__ o4,
    const float* __restrict__ os, const int* __restrict__ tgts)
{
    __shared__ unsigned s_min[8], s_max[8];

    const int lane = threadIdx.x & 31;
    const int wid  = threadIdx.x >> 5;
    const int row  = blockIdx.x * 8 + wid;
    const size_t base = (size_t)row * NC;

    const float4* A = reinterpret_cast<const float4*>(o1 + base);
    const float4* B = reinterpret_cast<const float4*>(o2 + base);
    const float4* C = reinterpret_cast<const float4*>(o3 + base);
    const float4* D = reinterpret_cast<const float4*>(o4 + base);
    const float4* S = reinterpret_cast<const float4*>(os + base);

    const int tg    = tgts[row];
    const int i4    = tg >> 2;       // owning float4 index
    const int oLane = i4 & 31;       // owning lane
    const int sub   = tg & 3;        // element within float4

    float E[5]  = {0, 0, 0, 0, 0};
    float S1[5] = {0, 0, 0, 0, 0};
    float S2[5] = {0, 0, 0, 0, 0};
    float Es1 = 0.0f, EsT = 0.0f;
    float m1[5], m2[5];
#pragma unroll
    for (int b = 0; b < 5; b++) { m1[b] = -CUDART_INF_F; m2[b] = -CUDART_INF_F; }
    float ms = -CUDART_INF_F;
    float c0 = 0, c1 = 0, c2 = 0, c3 = 0, cs = 0;   // captured target logits

#pragma unroll
    for (int k = 0; k < 8; k++) {
        const int idx = k * 32 + lane;
        if (idx < NV4) {
            float4 va = A[idx], vb = B[idx], vc = C[idx], vd = D[idx], vs = S[idx];
            const float za[4] = { va.x, va.y, va.z, va.w };
            const float zb[4] = { vb.x, vb.y, vb.z, vb.w };
            const float zc[4] = { vc.x, vc.y, vc.z, vc.w };
            const float zd[4] = { vd.x, vd.y, vd.z, vd.w };
            const float zs4[4] = { vs.x, vs.y, vs.z, vs.w };
            const bool own = (idx == i4);
#pragma unroll
            for (int j = 0; j < 4; j++) {
                const float zm = ((za[j] + zb[j]) + (zc[j] + zd[j])) * 0.25f;
                const float zs = zs4[j];
                const float zz[5] = { za[j], zb[j], zc[j], zd[j], zm };
                const float s2t = zs * ITKD;
#pragma unroll
                for (int b = 0; b < 5; b++) {
                    const float zt = zz[b] * ITKD;
                    const float e  = __expf(zt);
                    E[b]  += e;
                    S1[b]  = fmaf(e, zt,  S1[b]);
                    S2[b]  = fmaf(e, s2t, S2[b]);
                    if (zz[b] > m1[b]) { m2[b] = m1[b]; m1[b] = zz[b]; }
                    else               { m2[b] = fmaxf(m2[b], zz[b]); }
                }
                Es1 += __expf(zs);
                EsT += __expf(s2t);
                ms   = fmaxf(ms, zs);
                if (own && j == sub) { c0 = za[j]; c1 = zb[j]; c2 = zc[j]; c3 = zd[j]; cs = zs; }
            }
        }
    }

    // ---- warp reduction: 17 sums + 5 top-2 pairs + student max ----
#pragma unroll
    for (int off = 16; off; off >>= 1) {
#pragma unroll
        for (int b = 0; b < 5; b++) {
            E[b]  += __shfl_xor_sync(0xffffffffu, E[b],  off);
            S1[b] += __shfl_xor_sync(0xffffffffu, S1[b], off);
            S2[b] += __shfl_xor_sync(0xffffffffu, S2[b], off);
            float a1 = __shfl_xor_sync(0xffffffffu, m1[b], off);
            float a2 = __shfl_xor_sync(0xffffffffu, m2[b], off);
            merge2(m1[b], m2[b], a1, a2);
        }
        Es1 += __shfl_xor_sync(0xffffffffu, Es1, off);
        EsT += __shfl_xor_sync(0xffffffffu, EsT, off);
        ms   = fmaxf(ms, __shfl_xor_sync(0xffffffffu, ms, off));
    }

    // broadcast the captured target logits from the owning lane
    float g[5];
    g[0] = __shfl_sync(0xffffffffu, c0, oLane);
    g[1] = __shfl_sync(0xffffffffu, c1, oLane);
    g[2] = __shfl_sync(0xffffffffu, c2, oLane);
    g[3] = __shfl_sync(0xffffffffu, c3, oLane);
    const float zst = __shfl_sync(0xffffffffu, cs, oLane);
    g[4] = ((g[0] + g[1]) + (g[2] + g[3])) * 0.25f;

    // ---- per-row finalize (lane 0) ----
    if (lane == 0) {
        // margins (shift-invariant) + threshold softmax (T=6)
        float te[5], ts = 0.0f;
#pragma unroll
        for (int b = 0; b < 5; b++) {
            const float mg = (m1[b] == g[b]) ? (m1[b] - m2[b]) : 0.0f;
            te[b] = __expf(mg * ITTHR);
            ts += te[b];
        }
        const float invts = 1.0f / ts;
        (void)ms;

        const float CE   = __logf(Es1) - zst;
        const float lseT = __logf(EsT);

        float rb[16];
        rb[0] = CE;
#pragma unroll
        for (int b = 0; b < 5; b++) {
            const float iE = 1.0f / E[b];
            const float KD = TKD2 * ((S1[b] - S2[b]) * iE - __logf(E[b]) + lseT);
            rb[1 + b]  = te[b] * invts;
            rb[6 + b]  = g[b];
            rb[11 + b] = KD;
        }
        float4* out4 = reinterpret_cast<float4*>(g_rowbuf + (size_t)row * 16);
        out4[0] = make_float4(rb[0],  rb[1],  rb[2],  rb[3]);
        out4[1] = make_float4(rb[4],  rb[5],  rb[6],  rb[7]);
        out4[2] = make_float4(rb[8],  rb[9],  rb[10], rb[11]);
        out4[3] = make_float4(rb[12], rb[13], rb[14], rb[15]);

        const float gmin4 = fminf(fminf(g[0], g[1]), fminf(g[2], g[3]));
        const float mmax4 = fmaxf(fmaxf(m1[0], m1[1]), fmaxf(m1[2], m1[3]));
        s_min[wid] = encF(gmin4);
        s_max[wid] = encF(mmax4);
    }
    __syncthreads();
    if (threadIdx.x == 0) {
        unsigned mn = s_min[0], mx = s_max[0];
#pragma unroll
        for (int w = 1; w < 8; w++) { mn = min(mn, s_min[w]); mx = max(mx, s_max[w]); }
        atomicMin(&g_minEnc, mn);
        atomicMax(&g_maxEnc, mx);
    }
}

__global__ __launch_bounds__(256) void reduce_kernel() {
    __shared__ float rs[8];
    const float Cv = decF(g_minEnc);
    const float Mv = decF(g_maxEnc);
    const float shift = (Cv < 0.0f) ? (-Cv + 1e-5f) : 0.0f;
    const float inv   = 1.0f / (Mv + shift);

    int row = blockIdx.x * 256 + threadIdx.x;
    float loss = 0.0f;
    if (row < NB) {
        const float* r = g_rowbuf + (size_t)row * 16;
        float4 q0 = *reinterpret_cast<const float4*>(r);
        float4 q1 = *reinterpret_cast<const float4*>(r + 4);
        float4 q2 = *reinterpret_cast<const float4*>(r + 8);
        float4 q3 = *reinterpret_cast<const float4*>(r + 12);
        float a[16] = { q0.x,q0.y,q0.z,q0.w, q1.x,q1.y,q1.z,q1.w,
                        q2.x,q2.y,q2.z,q2.w, q3.x,q3.y,q3.z,q3.w };
        const float CE = a[0];
#pragma unroll
        for (int b = 0; b < 5; b++) {
            const float w2 = (a[6 + b] + shift) * inv;
            loss += a[1 + b] * ((1.0f - w2) * CE + w2 * a[11 + b]);
        }
    }
#pragma unroll
    for (int off = 16; off; off >>= 1)
        loss += __shfl_xor_sync(0xffffffffu, loss, off);
    if ((threadIdx.x & 31) == 0) rs[threadIdx.x >> 5] = loss;
    __syncthreads();
    if (threadIdx.x == 0) {
        float s = rs[0];
#pragma unroll
        for (int w = 1; w < 8; w++) s += rs[w];
        atomicAdd(&g_sum, s);
    }
}

__global__ void final_k(float* __restrict__ out) {
    out[0] = g_sum * (1.0f / (float)NB);
}

extern "C" void kernel_launch(void* const* d_in, const int* in_sizes, int n_in,
                              void* d_out, int out_size) {
    const float* o1 = (const float*)d_in[0];
    const float* o2 = (const float*)d_in[1];
    const float* o3 = (const float*)d_in[2];
    const float* o4 = (const float*)d_in[3];
    const float* os = (const float*)d_in[4];
    const int*   tg = (const int*)d_in[5];
    (void)in_sizes; (void)n_in; (void)out_size;

    init_k<<<1, 1>>>();
    row_kernel<<<NB / 8, 256>>>(o1, o2, o3, o4, os, tg);
    reduce_kernel<<<(NB + 255) / 256, 256>>>();
    final_k<<<1, 1>>>((float*)d_out);
}

// round 3
// speedup vs baseline: 1.8987x; 1.0733x over previous
#include <cuda_runtime.h>
#include <math_constants.h>

// Warp-per-row fused multi-teacher KD loss (single streaming pass, exp2-form,
// no atomics, 3 launches). See round notes: D-accumulator form,
// KD = 20*D/E + 400*(ln(EsT) - ln(E)).

namespace {
constexpr int NB = 8192;
constexpr int NC = 1000;
constexpr int NV4 = 250;                           // float4 per row
constexpr int NBLK = NB / 8;                       // row_kernel blocks (8 rows/block)
constexpr int RBLK = 32;                           // reduce blocks
constexpr float L2E   = 1.4426950408889634f;       // log2(e)
constexpr float C20   = 1.4426950408889634f / 20.0f;
constexpr float CTHR  = 1.4426950408889634f / 6.0f;
}

__device__ float g_rowbuf[NB * 16];
__device__ float g_bmin[NBLK];
__device__ float g_bmax[NBLK];
__device__ float g_partial[RBLK];

__global__ __launch_bounds__(256) void row_kernel(
    const float* __restrict__ o1, const float* __restrict__ o2,
    const float* __restrict__ o3, const float* __restrict__ o4,
    const float* __restrict__ os, const int* __restrict__ tgts)
{
    __shared__ float s_min[8], s_max[8];

    const int lane = threadIdx.x & 31;
    const int wid  = threadIdx.x >> 5;
    const int row  = blockIdx.x * 8 + wid;
    const size_t base = (size_t)row * NC;

    const float4* A = reinterpret_cast<const float4*>(o1 + base);
    const float4* B = reinterpret_cast<const float4*>(o2 + base);
    const float4* C = reinterpret_cast<const float4*>(o3 + base);
    const float4* D4 = reinterpret_cast<const float4*>(o4 + base);
    const float4* S = reinterpret_cast<const float4*>(os + base);

    float E[5]  = {0, 0, 0, 0, 0};
    float D[5]  = {0, 0, 0, 0, 0};
    float Es1 = 0.0f, EsT = 0.0f;
    float m1[5], m2[5];
#pragma unroll
    for (int b = 0; b < 5; b++) { m1[b] = -CUDART_INF_F; m2[b] = -CUDART_INF_F; }

#pragma unroll 2
    for (int k = 0; k < 8; k++) {
        const int idx = k * 32 + lane;
        if (idx < NV4) {
            float4 va = A[idx], vb = B[idx], vc = C[idx], vd = D4[idx], vs = S[idx];
            const float za[4]  = { va.x, va.y, va.z, va.w };
            const float zb[4]  = { vb.x, vb.y, vb.z, vb.w };
            const float zc[4]  = { vc.x, vc.y, vc.z, vc.w };
            const float zd[4]  = { vd.x, vd.y, vd.z, vd.w };
            const float zs4[4] = { vs.x, vs.y, vs.z, vs.w };
#pragma unroll
            for (int j = 0; j < 4; j++) {
                const float zs = zs4[j];
                Es1 += exp2f(zs * L2E);
                EsT += exp2f(zs * C20);
                const float zm = ((za[j] + zb[j]) + (zc[j] + zd[j])) * 0.25f;
                const float zz[5] = { za[j], zb[j], zc[j], zd[j], zm };
#pragma unroll
                for (int b = 0; b < 5; b++) {
                    const float z = zz[b];
                    const float e = exp2f(z * C20);
                    E[b] += e;
                    D[b]  = fmaf(e, z - zs, D[b]);
                    m2[b] = fmaxf(m2[b], fminf(m1[b], z));
                    m1[b] = fmaxf(m1[b], z);
                }
            }
        }
    }

    // direct gather of target logits (lines just streamed -> cache hits)
    const int tg = tgts[row];
    float g0 = 0, g1 = 0, g2 = 0, g3 = 0, zst = 0;
    if (lane == 0) {
        g0 = o1[base + tg]; g1 = o2[base + tg];
        g2 = o3[base + tg]; g3 = o4[base + tg];
        zst = os[base + tg];
    }

    // warp reduction: 12 sums + 5 top-2 pairs
#pragma unroll
    for (int off = 16; off; off >>= 1) {
#pragma unroll
        for (int b = 0; b < 5; b++) {
            E[b] += __shfl_xor_sync(0xffffffffu, E[b], off);
            D[b] += __shfl_xor_sync(0xffffffffu, D[b], off);
            float a1 = __shfl_xor_sync(0xffffffffu, m1[b], off);
            float a2 = __shfl_xor_sync(0xffffffffu, m2[b], off);
            m2[b] = fmaxf(m2[b], fminf(m1[b], a1));
            m2[b] = fmaxf(m2[b], a2);
            m1[b] = fmaxf(m1[b], a1);
        }
        Es1 += __shfl_xor_sync(0xffffffffu, Es1, off);
        EsT += __shfl_xor_sync(0xffffffffu, EsT, off);
    }

    if (lane == 0) {
        float g[5] = { g0, g1, g2, g3, ((g0 + g1) + (g2 + g3)) * 0.25f };

        // threshold softmax over margins (T=6); margins >= 0, no max-sub needed
        float te[5], ts = 0.0f;
#pragma unroll
        for (int b = 0; b < 5; b++) {
            const float mg = (m1[b] == g[b]) ? (m1[b] - m2[b]) : 0.0f;
            te[b] = exp2f(mg * CTHR);
            ts += te[b];
        }
        const float invts = 1.0f / ts;

        const float CE   = __logf(Es1) - zst;
        const float lseT = __logf(EsT);

        float rb[16];
        rb[0] = CE;
#pragma unroll
        for (int b = 0; b < 5; b++) {
            const float iE = 1.0f / E[b];
            const float KD = 20.0f * D[b] * iE + 400.0f * (lseT - __logf(E[b]));
            rb[1 + b]  = te[b] * invts;
            rb[6 + b]  = g[b];
            rb[11 + b] = KD;
        }
        float4* out4 = reinterpret_cast<float4*>(g_rowbuf + (size_t)row * 16);
        out4[0] = make_float4(rb[0],  rb[1],  rb[2],  rb[3]);
        out4[1] = make_float4(rb[4],  rb[5],  rb[6],  rb[7]);
        out4[2] = make_float4(rb[8],  rb[9],  rb[10], rb[11]);
        out4[3] = make_float4(rb[12], rb[13], rb[14], rb[15]);

        s_min[wid] = fminf(fminf(g[0], g[1]), fminf(g[2], g[3]));
        s_max[wid] = fmaxf(fmaxf(m1[0], m1[1]), fmaxf(m1[2], m1[3]));
    }
    __syncthreads();
    if (threadIdx.x == 0) {
        float mn = s_min[0], mx = s_max[0];
#pragma unroll
        for (int w = 1; w < 8; w++) { mn = fminf(mn, s_min[w]); mx = fmaxf(mx, s_max[w]); }
        g_bmin[blockIdx.x] = mn;
        g_bmax[blockIdx.x] = mx;
    }
}

__global__ __launch_bounds__(256) void reduce_kernel() {
    __shared__ float sm[8], sx[8], rs[8];
    const int t = threadIdx.x, lane = t & 31, wid = t >> 5;

    // every block redundantly reduces the 1024-entry min/max arrays (L2-hot)
    float mn = CUDART_INF_F, mx = -CUDART_INF_F;
#pragma unroll
    for (int i = 0; i < NBLK / 256; i++) {
        mn = fminf(mn, g_bmin[t + i * 256]);
        mx = fmaxf(mx, g_bmax[t + i * 256]);
    }
#pragma unroll
    for (int off = 16; off; off >>= 1) {
        mn = fminf(mn, __shfl_xor_sync(0xffffffffu, mn, off));
        mx = fmaxf(mx, __shfl_xor_sync(0xffffffffu, mx, off));
    }
    if (lane == 0) { sm[wid] = mn; sx[wid] = mx; }
    __syncthreads();
    float Cv = sm[0], Mv = sx[0];
#pragma unroll
    for (int w = 1; w < 8; w++) { Cv = fminf(Cv, sm[w]); Mv = fmaxf(Mv, sx[w]); }

    const float shift = (Cv < 0.0f) ? (-Cv + 1e-5f) : 0.0f;
    const float inv   = 1.0f / (Mv + shift);

    const int row = blockIdx.x * 256 + t;          // 32*256 == 8192, exact
    const float* r = g_rowbuf + (size_t)row * 16;
    float4 q0 = *reinterpret_cast<const float4*>(r);
    float4 q1 = *reinterpret_cast<const float4*>(r + 4);
    float4 q2 = *reinterpret_cast<const float4*>(r + 8);
    float4 q3 = *reinterpret_cast<const float4*>(r + 12);
    const float a[16] = { q0.x,q0.y,q0.z,q0.w, q1.x,q1.y,q1.z,q1.w,
                          q2.x,q2.y,q2.z,q2.w, q3.x,q3.y,q3.z,q3.w };
    const float CE = a[0];
    float loss = 0.0f;
#pragma unroll
    for (int b = 0; b < 5; b++) {
        const float w2 = (a[6 + b] + shift) * inv;
        loss += a[1 + b] * ((1.0f - w2) * CE + w2 * a[11 + b]);
    }
#pragma unroll
    for (int off = 16; off; off >>= 1)
        loss += __shfl_xor_sync(0xffffffffu, loss, off);
    if (lane == 0) rs[wid] = loss;
    __syncthreads();
    if (t == 0) {
        float s = rs[0];
#pragma unroll
        for (int w = 1; w < 8; w++) s += rs[w];
        g_partial[blockIdx.x] = s;
    }
}

__global__ void final_k(float* __restrict__ out) {
    float v = g_partial[threadIdx.x];              // 32 threads, exact
#pragma unroll
    for (int off = 16; off; off >>= 1)
        v += __shfl_xor_sync(0xffffffffu, v, off);
    if (threadIdx.x == 0) out[0] = v * (1.0f / (float)NB);
}

extern "C" void kernel_launch(void* const* d_in, const int* in_sizes, int n_in,
                              void* d_out, int out_size) {
    const float* o1 = (const float*)d_in[0];
    const float* o2 = (const float*)d_in[1];
    const float* o3 = (const float*)d_in[2];
    const float* o4 = (const float*)d_in[3];
    const float* os = (const float*)d_in[4];
    const int*   tg = (const int*)d_in[5];
    (void)in_sizes; (void)n_in; (void)out_size;

    row_kernel<<<NBLK, 256>>>(o1, o2, o3, o4, os, tg);
    reduce_kernel<<<RBLK, 256>>>();
    final_k<<<1, 32>>>((float*)d_out);
}

// round 4
// speedup vs baseline: 1.9905x; 1.0483x over previous
#include <cuda_runtime.h>
#include <math_constants.h>

// Warp-per-row fused multi-teacher KD loss (single streaming pass, exp2-form,
// no atomics, 3 launches). R3: occupancy push — launch_bounds(256,4) to cap
// regs at 64 (4 blocks/SM), unroll-1 main loop, peeled tail.

namespace {
constexpr int NB = 8192;
constexpr int NC = 1000;
constexpr int NV4 = 250;                           // float4 per row
constexpr int NBLK = NB / 8;                       // row_kernel blocks (8 rows/block)
constexpr int RBLK = 32;                           // reduce blocks
constexpr float L2E   = 1.4426950408889634f;       // log2(e)
constexpr float C20   = 1.4426950408889634f / 20.0f;
constexpr float CTHR  = 1.4426950408889634f / 6.0f;
}

__device__ float g_rowbuf[NB * 16];
__device__ float g_bmin[NBLK];
__device__ float g_bmax[NBLK];
__device__ float g_partial[RBLK];

__global__ __launch_bounds__(256, 4) void row_kernel(
    const float* __restrict__ o1, const float* __restrict__ o2,
    const float* __restrict__ o3, const float* __restrict__ o4,
    const float* __restrict__ os, const int* __restrict__ tgts)
{
    __shared__ float s_min[8], s_max[8];

    const int lane = threadIdx.x & 31;
    const int wid  = threadIdx.x >> 5;
    const int row  = blockIdx.x * 8 + wid;
    const size_t base = (size_t)row * NC;

    const float4* A  = reinterpret_cast<const float4*>(o1 + base) + lane;
    const float4* B  = reinterpret_cast<const float4*>(o2 + base) + lane;
    const float4* C  = reinterpret_cast<const float4*>(o3 + base) + lane;
    const float4* D4 = reinterpret_cast<const float4*>(o4 + base) + lane;
    const float4* S  = reinterpret_cast<const float4*>(os + base) + lane;

    float E[5]  = {0, 0, 0, 0, 0};
    float D[5]  = {0, 0, 0, 0, 0};
    float Es1 = 0.0f, EsT = 0.0f;
    float m1[5], m2[5];
#pragma unroll
    for (int b = 0; b < 5; b++) { m1[b] = -CUDART_INF_F; m2[b] = -CUDART_INF_F; }

    // one float4-bundle of work (all 5 tensors), accumulating into the state
    auto body = [&](float4 va, float4 vb, float4 vc, float4 vd, float4 vs) {
        const float za[4]  = { va.x, va.y, va.z, va.w };
        const float zb[4]  = { vb.x, vb.y, vb.z, vb.w };
        const float zc[4]  = { vc.x, vc.y, vc.z, vc.w };
        const float zd[4]  = { vd.x, vd.y, vd.z, vd.w };
        const float zs4[4] = { vs.x, vs.y, vs.z, vs.w };
#pragma unroll
        for (int j = 0; j < 4; j++) {
            const float zs = zs4[j];
            Es1 += exp2f(zs * L2E);
            EsT += exp2f(zs * C20);
            const float zm = ((za[j] + zb[j]) + (zc[j] + zd[j])) * 0.25f;
            const float zz[5] = { za[j], zb[j], zc[j], zd[j], zm };
#pragma unroll
            for (int b = 0; b < 5; b++) {
                const float z = zz[b];
                const float e = exp2f(z * C20);
                E[b] += e;
                D[b]  = fmaf(e, z - zs, D[b]);
                m2[b] = fmaxf(m2[b], fminf(m1[b], z));
                m1[b] = fmaxf(m1[b], z);
            }
        }
    };

#pragma unroll 1
    for (int k = 0; k < 7; k++) {
        const int o = k * 32;
        body(A[o], B[o], C[o], D4[o], S[o]);
    }
    if (lane < NV4 - 224) {                        // tail: idx = 224+lane < 250
        body(A[224], B[224], C[224], D4[224], S[224]);
    }

    // direct gather of target logits (lines just streamed -> cache hits)
    const int tg = tgts[row];
    float g0 = 0, g1 = 0, g2 = 0, g3 = 0, zst = 0;
    if (lane == 0) {
        g0 = o1[base + tg]; g1 = o2[base + tg];
        g2 = o3[base + tg]; g3 = o4[base + tg];
        zst = os[base + tg];
    }

    // warp reduction: 12 sums + 5 top-2 pairs
#pragma unroll
    for (int off = 16; off; off >>= 1) {
#pragma unroll
        for (int b = 0; b < 5; b++) {
            E[b] += __shfl_xor_sync(0xffffffffu, E[b], off);
            D[b] += __shfl_xor_sync(0xffffffffu, D[b], off);
            float a1 = __shfl_xor_sync(0xffffffffu, m1[b], off);
            float a2 = __shfl_xor_sync(0xffffffffu, m2[b], off);
            m2[b] = fmaxf(m2[b], fminf(m1[b], a1));
            m2[b] = fmaxf(m2[b], a2);
            m1[b] = fmaxf(m1[b], a1);
        }
        Es1 += __shfl_xor_sync(0xffffffffu, Es1, off);
        EsT += __shfl_xor_sync(0xffffffffu, EsT, off);
    }

    if (lane == 0) {
        float g[5] = { g0, g1, g2, g3, ((g0 + g1) + (g2 + g3)) * 0.25f };

        // threshold softmax over margins (T=6); margins >= 0, no max-sub needed
        float te[5], ts = 0.0f;
#pragma unroll
        for (int b = 0; b < 5; b++) {
            const float mg = (m1[b] == g[b]) ? (m1[b] - m2[b]) : 0.0f;
            te[b] = exp2f(mg * CTHR);
            ts += te[b];
        }
        const float invts = 1.0f / ts;

        const float CE   = __logf(Es1) - zst;
        const float lseT = __logf(EsT);

        float rb[16];
        rb[0] = CE;
#pragma unroll
        for (int b = 0; b < 5; b++) {
            const float iE = 1.0f / E[b];
            const float KD = 20.0f * D[b] * iE + 400.0f * (lseT - __logf(E[b]));
            rb[1 + b]  = te[b] * invts;
            rb[6 + b]  = g[b];
            rb[11 + b] = KD;
        }
        float4* out4 = reinterpret_cast<float4*>(g_rowbuf + (size_t)row * 16);
        out4[0] = make_float4(rb[0],  rb[1],  rb[2],  rb[3]);
        out4[1] = make_float4(rb[4],  rb[5],  rb[6],  rb[7]);
        out4[2] = make_float4(rb[8],  rb[9],  rb[10], rb[11]);
        out4[3] = make_float4(rb[12], rb[13], rb[14], rb[15]);

        s_min[wid] = fminf(fminf(g[0], g[1]), fminf(g[2], g[3]));
        s_max[wid] = fmaxf(fmaxf(m1[0], m1[1]), fmaxf(m1[2], m1[3]));
    }
    __syncthreads();
    if (threadIdx.x == 0) {
        float mn = s_min[0], mx = s_max[0];
#pragma unroll
        for (int w = 1; w < 8; w++) { mn = fminf(mn, s_min[w]); mx = fmaxf(mx, s_max[w]); }
        g_bmin[blockIdx.x] = mn;
        g_bmax[blockIdx.x] = mx;
    }
}

__global__ __launch_bounds__(256) void reduce_kernel() {
    __shared__ float sm[8], sx[8], rs[8];
    const int t = threadIdx.x, lane = t & 31, wid = t >> 5;

    // every block redundantly reduces the 1024-entry min/max arrays (L2-hot)
    float mn = CUDART_INF_F, mx = -CUDART_INF_F;
#pragma unroll
    for (int i = 0; i < NBLK / 256; i++) {
        mn = fminf(mn, g_bmin[t + i * 256]);
        mx = fmaxf(mx, g_bmax[t + i * 256]);
    }
#pragma unroll
    for (int off = 16; off; off >>= 1) {
        mn = fminf(mn, __shfl_xor_sync(0xffffffffu, mn, off));
        mx = fmaxf(mx, __shfl_xor_sync(0xffffffffu, mx, off));
    }
    if (lane == 0) { sm[wid] = mn; sx[wid] = mx; }
    __syncthreads();
    float Cv = sm[0], Mv = sx[0];
#pragma unroll
    for (int w = 1; w < 8; w++) { Cv = fminf(Cv, sm[w]); Mv = fmaxf(Mv, sx[w]); }

    const float shift = (Cv < 0.0f) ? (-Cv + 1e-5f) : 0.0f;
    const float inv   = 1.0f / (Mv + shift);

    const int row = blockIdx.x * 256 + t;          // 32*256 == 8192, exact
    const float* r = g_rowbuf + (size_t)row * 16;
    float4 q0 = *reinterpret_cast<const float4*>(r);
    float4 q1 = *reinterpret_cast<const float4*>(r + 4);
    float4 q2 = *reinterpret_cast<const float4*>(r + 8);
    float4 q3 = *reinterpret_cast<const float4*>(r + 12);
    const float a[16] = { q0.x,q0.y,q0.z,q0.w, q1.x,q1.y,q1.z,q1.w,
                          q2.x,q2.y,q2.z,q2.w, q3.x,q3.y,q3.z,q3.w };
    const float CE = a[0];
    float loss = 0.0f;
#pragma unroll
    for (int b = 0; b < 5; b++) {
        const float w2 = (a[6 + b] + shift) * inv;
        loss += a[1 + b] * ((1.0f - w2) * CE + w2 * a[11 + b]);
    }
#pragma unroll
    for (int off = 16; off; off >>= 1)
        loss += __shfl_xor_sync(0xffffffffu, loss, off);
    if (lane == 0) rs[wid] = loss;
    __syncthreads();
    if (t == 0) {
        float s = rs[0];
#pragma unroll
        for (int w = 1; w < 8; w++) s += rs[w];
        g_partial[blockIdx.x] = s;
    }
}

__global__ void final_k(float* __restrict__ out) {
    float v = g_partial[threadIdx.x];              // 32 threads, exact
#pragma unroll
    for (int off = 16; off; off >>= 1)
        v += __shfl_xor_sync(0xffffffffu, v, off);
    if (threadIdx.x == 0) out[0] = v * (1.0f / (float)NB);
}

extern "C" void kernel_launch(void* const* d_in, const int* in_sizes, int n_in,
                              void* d_out, int out_size) {
    const float* o1 = (const float*)d_in[0];
    const float* o2 = (const float*)d_in[1];
    const float* o3 = (const float*)d_in[2];
    const float* o4 = (const float*)d_in[3];
    const float* os = (const float*)d_in[4];
    const int*   tg = (const int*)d_in[5];
    (void)in_sizes; (void)n_in; (void)out_size;

    row_kernel<<<NBLK, 256>>>(o1, o2, o3, o4, os, tg);
    reduce_kernel<<<RBLK, 256>>>();
    final_k<<<1, 32>>>((float*)d_out);
}